// round 9
// baseline (speedup 1.0000x reference)
#include <cuda_runtime.h>
#include <cuda_fp16.h>

#define B 8
#define S 512
#define E 64
#define H 8

// ---- dynamic smem layout (bytes) ------------------------------------------
#define KS_STRIDE 8208                 // per-head: 512*16B rows + 16B pad (banks: 4h quads)
#define KS_BYTES  (8 * KS_STRIDE)      // 65664
#define WS_OFF    KS_BYTES
#define WS_ROW    68                   // floats per W row (pad)
#define WS_BYTES  (64 * WS_ROW * 4)    // 17408
#define CS_OFF    (WS_OFF + WS_BYTES)
#define CS_ROW    68                   // floats per ctx row (pad)
#define CS_BYTES  (32 * CS_ROW * 4)    // 8704
#define BS_OFF    (CS_OFF + CS_BYTES)
#define SMEM_TOTAL (BS_OFF + 256)      // 92032

__device__ __forceinline__ unsigned h2u(__half2 h) { return *reinterpret_cast<unsigned*>(&h); }
__device__ __forceinline__ __half2 u2h(unsigned u) { return *reinterpret_cast<__half2*>(&u); }

__device__ __forceinline__ __half2 h2ex2(__half2 v) {
    unsigned r, a = h2u(v);
    asm("ex2.approx.f16x2 %0, %1;" : "=r"(r) : "r"(a));
    return u2h(r);
}

// ---------------------------------------------------------------------------
// One kernel, one wave: block = (b, 32-query chunk), all 8 heads.
// Phase A: build K (analytic cos prefix products) for all heads -> smem fp16.
// Phase B: attention, fp16 dot + fp16 chunked accumulation (promote /16 keys).
// Phase C: in-block output projection (ctx complete per query -> out).
// ---------------------------------------------------------------------------
__global__ void __launch_bounds__(512) fused_kernel(
    const float* __restrict__ x,      // [B, S, E]
    const float* __restrict__ theta,  // [8]
    const float* __restrict__ W,      // [64, 64] (e, k)
    const float* __restrict__ bo,     // [64]
    float* __restrict__ out)          // [B*S, 64]
{
    extern __shared__ char sm[];
    float* Ws = (float*)(sm + WS_OFF);
    float* Cs = (float*)(sm + CS_OFF);
    float* bs = (float*)(sm + BS_OFF);

    const int tid   = threadIdx.x;    // 0..511
    const int bid   = blockIdx.x;     // 0..127
    const int b     = bid >> 4;
    const int chunk = bid & 15;       // 32-query chunk

    // ---- stage W + bias (own smem region; overlaps with build) ----
    {
        const float4* W4 = (const float4*)W;
#pragma unroll
        for (int i = tid; i < 1024; i += 512) {
            float4 w = __ldg(W4 + i);
            int e = i >> 4, k = (i & 15) * 4;
            *(float4*)(Ws + e * WS_ROW + k) = w;
        }
        if (tid < 16) *(float4*)(bs + tid * 4) = __ldg((const float4*)bo + tid);
    }

    float th[8];
#pragma unroll
    for (int j = 0; j < 8; ++j) th[j] = __ldg(theta + j);

    // ---- Phase A: build fp16 K for all 8 heads ----
    // thread handles one 4-float chunk of one x row; lane pairs (m, m^1) hold
    // the two halves of one head segment and exchange via shfl.
    const float4* x4 = (const float4*)x + (size_t)b * (S * E / 4);
#pragma unroll
    for (int j = 0; j < 16; ++j) {
        int m = j * 512 + tid;        // 0..8191
        int r = m >> 4;               // key row 0..511
        int c = m & 15;               // float4 chunk 0..15; head = c>>1
        float4 v = __ldg(x4 + m);
        int tb = (c & 1) * 4;         // theta offset (period 8)
        float f0 = __cosf(v.x + th[tb + 0]);
        float f1 = __cosf(v.y + th[tb + 1]);
        float f2 = __cosf(v.z + th[tb + 2]);
        float f3 = __cosf(v.w + th[tb + 3]);
        float g0 = __shfl_xor_sync(0xffffffffu, f0, 1);
        float g1 = __shfl_xor_sync(0xffffffffu, f1, 1);
        float g2 = __shfl_xor_sync(0xffffffffu, f2, 1);
        float g3 = __shfl_xor_sync(0xffffffffu, f3, 1);
        bool hi = (c & 1);
        float c0 = hi ? g0 : f0, c1 = hi ? g1 : f1;
        float c2 = hi ? g2 : f2, c3 = hi ? g3 : f3;
        float c4 = hi ? f0 : g0, c5 = hi ? f1 : g1;
        float c6 = hi ? f2 : g2, c7 = hi ? f3 : g3;
        float q1 = c0 * c1, q2 = q1 * c2, q3 = q2 * c3;
        float q4 = q3 * c4, q5 = q4 * c5, q6 = q5 * c6, q7 = q6 * c7;
        float t01 = c1 * c2, t23 = c3 * c4, t45 = c5 * c6;
        float q0 = t01 * t23 * t45 * c7;
        float a0 = hi ? q4 : q0, a1 = hi ? q5 : q1;
        float a2 = hi ? q6 : q2, a3 = hi ? q7 : q3;
        __half2 p0 = __floats2half2_rn(a0, a1);
        __half2 p1 = __floats2half2_rn(a2, a3);
        char* dst = sm + (c >> 1) * KS_STRIDE + r * 16 + (c & 1) * 8;
        *(uint2*)dst = make_uint2(h2u(p0), h2u(p1));
    }
    __syncthreads();

    // ---- Phase B: attention ----
    // tid = h*64 + qq*2 + g : head h, query qq (0..31), key-split g (0..1).
    const int h  = tid >> 6;
    const int rr = tid & 63;
    const int qq = rr >> 1;
    const int g  = rr & 1;
    const int sq = chunk * 32 + qq;   // query's key-row index

    uint4 qv = *(const uint4*)(sm + h * KS_STRIDE + sq * 16);
    const __half2 sch = __float2half2_rn(0.51010202f); // (1/sqrt(8))*log2(e)
    __half2 qh0 = __hmul2(u2h(qv.x), sch);
    __half2 qh1 = __hmul2(u2h(qv.y), sch);
    __half2 qh2 = __hmul2(u2h(qv.z), sch);
    __half2 qh3 = __hmul2(u2h(qv.w), sch);

    const __half2 hz = __float2half2_rn(0.f);
    float F[8] = {0.f, 0.f, 0.f, 0.f, 0.f, 0.f, 0.f, 0.f};
    float lf = 0.f;

    const char* kp = sm + h * KS_STRIDE + g * 16;   // keys s = 2i + g
    for (int o = 0; o < 16; ++o) {
        __half2 a0 = hz, a1 = hz, a2 = hz, a3 = hz, l2 = hz;
        const char* kpo = kp + o * 512;             // 16 keys * 32B
#pragma unroll
        for (int i = 0; i < 16; ++i) {
            uint4 kv = *(const uint4*)(kpo + i * 32);
            __half2 k0 = u2h(kv.x), k1 = u2h(kv.y), k2 = u2h(kv.z), k3 = u2h(kv.w);
            __half2 d = __hmul2(qh0, k0);
            d = __hfma2(qh1, k1, d);
            d = __hfma2(qh2, k2, d);
            d = __hfma2(qh3, k3, d);
            __half2 ds = __hadd2(d, __lowhigh2highlow(d)); // both halves = score
            __half2 w2 = h2ex2(ds);                        // 2^score in both halves
            l2 = __hadd2(l2, w2);
            a0 = __hfma2(w2, k0, a0);
            a1 = __hfma2(w2, k1, a1);
            a2 = __hfma2(w2, k2, a2);
            a3 = __hfma2(w2, k3, a3);
        }
        // promote chunk to fp32 (bounds fp16 accumulation error)
        float2 t;
        t = __half22float2(a0); F[0] += t.x; F[1] += t.y;
        t = __half22float2(a1); F[2] += t.x; F[3] += t.y;
        t = __half22float2(a2); F[4] += t.x; F[5] += t.y;
        t = __half22float2(a3); F[6] += t.x; F[7] += t.y;
        lf += __low2float(l2);
    }

    // reduce over the g pair (adjacent lanes)
    float FF[9] = {F[0], F[1], F[2], F[3], F[4], F[5], F[6], F[7], lf};
#pragma unroll
    for (int v = 0; v < 9; ++v)
        FF[v] += __shfl_xor_sync(0xffffffffu, FF[v], 1);

    if (g == 0) {
        float inv = 1.f / FF[8];
        float* cp = Cs + qq * CS_ROW + h * 8;
        *(float4*)(cp + 0) = make_float4(FF[0] * inv, FF[1] * inv, FF[2] * inv, FF[3] * inv);
        *(float4*)(cp + 4) = make_float4(FF[4] * inv, FF[5] * inv, FF[6] * inv, FF[7] * inv);
    }
    __syncthreads();

    // ---- Phase C: projection. out[n,e] = sum_c ctx[n,c]*W[e,c] + b[e] ----
    {
        const int q2 = tid >> 4;          // 0..31
        const int e0 = (tid & 15) * 4;    // 4 outputs
        const float* crow = Cs + q2 * CS_ROW;
        float4 acc = *(const float4*)(bs + e0);
#pragma unroll
        for (int c4 = 0; c4 < 16; ++c4) {
            float4 cv = *(const float4*)(crow + c4 * 4);   // broadcast
            const float* wb = Ws + c4 * 4;
            float4 w0 = *(const float4*)(wb + (e0 + 0) * WS_ROW);
            float4 w1 = *(const float4*)(wb + (e0 + 1) * WS_ROW);
            float4 w2 = *(const float4*)(wb + (e0 + 2) * WS_ROW);
            float4 w3 = *(const float4*)(wb + (e0 + 3) * WS_ROW);
            acc.x = fmaf(cv.x, w0.x, fmaf(cv.y, w0.y, fmaf(cv.z, w0.z, fmaf(cv.w, w0.w, acc.x))));
            acc.y = fmaf(cv.x, w1.x, fmaf(cv.y, w1.y, fmaf(cv.z, w1.z, fmaf(cv.w, w1.w, acc.y))));
            acc.z = fmaf(cv.x, w2.x, fmaf(cv.y, w2.y, fmaf(cv.z, w2.z, fmaf(cv.w, w2.w, acc.z))));
            acc.w = fmaf(cv.x, w3.x, fmaf(cv.y, w3.y, fmaf(cv.z, w3.z, fmaf(cv.w, w3.w, acc.w))));
        }
        const int n = b * S + chunk * 32 + q2;
        *(float4*)(out + (size_t)n * 64 + e0) = acc;
    }
}

extern "C" void kernel_launch(void* const* d_in, const int* in_sizes, int n_in,
                              void* d_out, int out_size)
{
    const float* x     = (const float*)d_in[0];  // [8, 512, 64]
    const float* theta = (const float*)d_in[1];  // [8]
    const float* W_o   = (const float*)d_in[2];  // [64, 64]
    const float* b_o   = (const float*)d_in[3];  // [64]
    float* out = (float*)d_out;

    cudaFuncSetAttribute(fused_kernel,
                         cudaFuncAttributeMaxDynamicSharedMemorySize, SMEM_TOTAL);
    fused_kernel<<<128, 512, SMEM_TOTAL>>>(x, theta, W_o, b_o, out);
}

// round 11
// speedup vs baseline: 1.1648x; 1.1648x over previous
#include <cuda_runtime.h>
#include <cuda_fp16.h>

#define B 8
#define S 512
#define E 64
#define H 8

// ---- dynamic smem layout (bytes) ------------------------------------------
#define KS_STRIDE 8208                 // per-head: 512*16B rows + 16B pad
#define KS_BYTES  (8 * KS_STRIDE)      // 65664
#define WS_OFF    KS_BYTES
#define WS_ROW    65                   // floats per W row (pad-65: scalar LDS banks (e+k)%32)
#define WS_BYTES  (64 * WS_ROW * 4)    // 16640
#define CS_OFF    (WS_OFF + WS_BYTES)
#define CS_ROW    68                   // floats per ctx row (16B-aligned float4 stores)
#define CS_BYTES  (16 * CS_ROW * 4)    // 4352
#define BS_OFF    (CS_OFF + CS_BYTES)
#define SMEM_TOTAL (BS_OFF + 256)      // 86912 -> 2 blocks/SM

__device__ __forceinline__ unsigned h2u(__half2 h) { return *reinterpret_cast<unsigned*>(&h); }
__device__ __forceinline__ __half2 u2h(unsigned u) { return *reinterpret_cast<__half2*>(&u); }

__device__ __forceinline__ __half2 h2ex2(__half2 v) {
    unsigned r, a = h2u(v);
    asm("ex2.approx.f16x2 %0, %1;" : "=r"(r) : "r"(a));
    return u2h(r);
}

// ---------------------------------------------------------------------------
// One kernel: block = (b, 16-query chunk), all 8 heads. 256 blocks x 512 thr
// -> 2 blocks/SM, 32 warps/SM (fixes R9's 16-warp residency cap).
// Phase A: build fp16 K (analytic cos prefix products) for all heads.
// Phase B: attention, fp16 dot + chunked fp32 promotion; key split g=0..3.
// Phase C: in-block projection (pad-65 scalar W, conflict-free).
// ---------------------------------------------------------------------------
__global__ void __launch_bounds__(512) fused_kernel(
    const float* __restrict__ x,      // [B, S, E]
    const float* __restrict__ theta,  // [8]
    const float* __restrict__ W,      // [64, 64] (e, k)
    const float* __restrict__ bo,     // [64]
    float* __restrict__ out)          // [B*S, 64]
{
    extern __shared__ char sm[];
    float* Ws = (float*)(sm + WS_OFF);
    float* Cs = (float*)(sm + CS_OFF);
    float* bs = (float*)(sm + BS_OFF);

    const int tid   = threadIdx.x;    // 0..511
    const int bid   = blockIdx.x;     // 0..255
    const int b     = bid >> 5;
    const int chunk = bid & 31;       // 16-query chunk

    // ---- stage W (pad-65 scalar) + bias ----
    for (int i = tid; i < 64 * 64; i += 512) {
        int e = i >> 6, k = i & 63;
        Ws[e * WS_ROW + k] = __ldg(W + i);
    }
    if (tid < 64) bs[tid] = __ldg(bo + tid);

    float th[8];
#pragma unroll
    for (int j = 0; j < 8; ++j) th[j] = __ldg(theta + j);

    // ---- Phase A: build fp16 K for all 8 heads ----
    const float4* x4 = (const float4*)x + (size_t)b * (S * E / 4);
#pragma unroll
    for (int j = 0; j < 16; ++j) {
        int m = j * 512 + tid;        // 0..8191
        int r = m >> 4;               // key row 0..511
        int c = m & 15;               // float4 chunk; head = c>>1
        float4 v = __ldg(x4 + m);
        int tb = (c & 1) * 4;
        float f0 = __cosf(v.x + th[tb + 0]);
        float f1 = __cosf(v.y + th[tb + 1]);
        float f2 = __cosf(v.z + th[tb + 2]);
        float f3 = __cosf(v.w + th[tb + 3]);
        float g0 = __shfl_xor_sync(0xffffffffu, f0, 1);
        float g1 = __shfl_xor_sync(0xffffffffu, f1, 1);
        float g2 = __shfl_xor_sync(0xffffffffu, f2, 1);
        float g3 = __shfl_xor_sync(0xffffffffu, f3, 1);
        bool hi = (c & 1);
        float c0 = hi ? g0 : f0, c1 = hi ? g1 : f1;
        float c2 = hi ? g2 : f2, c3 = hi ? g3 : f3;
        float c4 = hi ? f0 : g0, c5 = hi ? f1 : g1;
        float c6 = hi ? f2 : g2, c7 = hi ? f3 : g3;
        float q1 = c0 * c1, q2 = q1 * c2, q3 = q2 * c3;
        float q4 = q3 * c4, q5 = q4 * c5, q6 = q5 * c6, q7 = q6 * c7;
        float t01 = c1 * c2, t23 = c3 * c4, t45 = c5 * c6;
        float q0 = t01 * t23 * t45 * c7;
        float a0 = hi ? q4 : q0, a1 = hi ? q5 : q1;
        float a2 = hi ? q6 : q2, a3 = hi ? q7 : q3;
        __half2 p0 = __floats2half2_rn(a0, a1);
        __half2 p1 = __floats2half2_rn(a2, a3);
        char* dst = sm + (c >> 1) * KS_STRIDE + r * 16 + (c & 1) * 8;
        *(uint2*)dst = make_uint2(h2u(p0), h2u(p1));
    }
    __syncthreads();

    // ---- Phase B: attention ----
    // tid = h*64 + qq*4 + g : head h, query qq (0..15), key-split g (0..3).
    const int h  = tid >> 6;
    const int rr = tid & 63;
    const int qq = rr >> 2;
    const int g  = rr & 3;
    const int sq = chunk * 16 + qq;   // query's key-row index

    uint4 qv = *(const uint4*)(sm + h * KS_STRIDE + sq * 16);
    const __half2 sch = __float2half2_rn(0.51010202f); // (1/sqrt(8))*log2(e)
    __half2 qh0 = __hmul2(u2h(qv.x), sch);
    __half2 qh1 = __hmul2(u2h(qv.y), sch);
    __half2 qh2 = __hmul2(u2h(qv.z), sch);
    __half2 qh3 = __hmul2(u2h(qv.w), sch);

    const __half2 hz = __float2half2_rn(0.f);
    float F[8] = {0.f, 0.f, 0.f, 0.f, 0.f, 0.f, 0.f, 0.f};
    float lf = 0.f;

    const char* kp = sm + h * KS_STRIDE + g * 16;   // keys s = 4i + g
    for (int o = 0; o < 8; ++o) {
        __half2 a0 = hz, a1 = hz, a2 = hz, a3 = hz, l2 = hz;
        const char* kpo = kp + o * 1024;            // 16 keys * 64B
#pragma unroll
        for (int i = 0; i < 16; ++i) {
            uint4 kv = *(const uint4*)(kpo + i * 64);
            __half2 k0 = u2h(kv.x), k1 = u2h(kv.y), k2 = u2h(kv.z), k3 = u2h(kv.w);
            __half2 d = __hmul2(qh0, k0);
            d = __hfma2(qh1, k1, d);
            d = __hfma2(qh2, k2, d);
            d = __hfma2(qh3, k3, d);
            __half2 ds = __hadd2(d, __lowhigh2highlow(d));
            __half2 w2 = h2ex2(ds);
            l2 = __hadd2(l2, w2);
            a0 = __hfma2(w2, k0, a0);
            a1 = __hfma2(w2, k1, a1);
            a2 = __hfma2(w2, k2, a2);
            a3 = __hfma2(w2, k3, a3);
        }
        float2 t;
        t = __half22float2(a0); F[0] += t.x; F[1] += t.y;
        t = __half22float2(a1); F[2] += t.x; F[3] += t.y;
        t = __half22float2(a2); F[4] += t.x; F[5] += t.y;
        t = __half22float2(a3); F[6] += t.x; F[7] += t.y;
        lf += __low2float(l2);
    }

    // reduce across the 4 split lanes (contiguous within the warp)
    float FF[9] = {F[0], F[1], F[2], F[3], F[4], F[5], F[6], F[7], lf};
#pragma unroll
    for (int v = 0; v < 9; ++v) {
        FF[v] += __shfl_xor_sync(0xffffffffu, FF[v], 1);
        FF[v] += __shfl_xor_sync(0xffffffffu, FF[v], 2);
    }

    if (g == 0) {
        float inv = 1.f / FF[8];
        float* cp = Cs + qq * CS_ROW + h * 8;
        *(float4*)(cp + 0) = make_float4(FF[0] * inv, FF[1] * inv, FF[2] * inv, FF[3] * inv);
        *(float4*)(cp + 4) = make_float4(FF[4] * inv, FF[5] * inv, FF[6] * inv, FF[7] * inv);
    }
    __syncthreads();

    // ---- Phase C: projection. out[n,e] = sum_k ctx[n,k]*W[e,k] + b[e] ----
    // 16 rows x 32 lanes; lane owns outputs e=lane, e=lane+32.
    // Ws scalar reads: banks (e + k) % 32 -> conflict-free; Cs broadcast.
    {
        const int q2   = tid >> 5;        // 0..15
        const int lane = tid & 31;
        const float* crow = Cs + q2 * CS_ROW;
        float acc0 = bs[lane];
        float acc1 = bs[lane + 32];
#pragma unroll 8
        for (int k = 0; k < 64; ++k) {
            float c  = crow[k];                       // broadcast
            acc0 = fmaf(c, Ws[lane * WS_ROW + k], acc0);
            acc1 = fmaf(c, Ws[(lane + 32) * WS_ROW + k], acc1);
        }
        const int n = b * S + chunk * 16 + q2;
        out[(size_t)n * 64 + lane]      = acc0;
        out[(size_t)n * 64 + lane + 32] = acc1;
    }
}

extern "C" void kernel_launch(void* const* d_in, const int* in_sizes, int n_in,
                              void* d_out, int out_size)
{
    const float* x     = (const float*)d_in[0];  // [8, 512, 64]
    const float* theta = (const float*)d_in[1];  // [8]
    const float* W_o   = (const float*)d_in[2];  // [64, 64]
    const float* b_o   = (const float*)d_in[3];  // [64]
    float* out = (float*)d_out;

    cudaFuncSetAttribute(fused_kernel,
                         cudaFuncAttributeMaxDynamicSharedMemorySize, SMEM_TOTAL);
    fused_kernel<<<256, 512, SMEM_TOTAL>>>(x, theta, W_o, b_o, out);
}